// round 2
// baseline (speedup 1.0000x reference)
#include <cuda_runtime.h>

// Problem constants (fixed-shape problem: pred (B,24,160,160), targets (N,6))
#define HGT   160
#define WID   160
#define HW    (HGT * WID)          // 25600
#define HW4   (HW / 4)             // 6400 float4 per plane
#define NANCH 3
#define NCLS  3
#define NCH   (NANCH * 8)          // 24 channels

#define CONF_BLOCKS 608
#define CONF_THREADS 256
#define MAX_TGT 2048

// Scratch: per-block partial sums of sigma(conf)^2. Overwritten every call,
// so no zeroing needed and the launch stays deterministic.
__device__ float g_partials[CONF_BLOCKS];

__device__ __forceinline__ float sig_fast(float x) {
    return 1.0f / (1.0f + __expf(-x));
}

// ---------------------------------------------------------------------------
// Kernel 1: dense pass over ONLY the conf channels (chan = b*24 + a*8 + 4).
// Computes sum of sigmoid(x)^2 over all B*A*H*W conf elements.
// ---------------------------------------------------------------------------
__global__ void __launch_bounds__(CONF_THREADS)
conf_kernel(const float* __restrict__ pred, int nplanes /* B*A */) {
    const int nf4 = nplanes * HW4;
    float acc = 0.0f;
    const float4* __restrict__ p4 = (const float4*)pred;

    for (int g = blockIdx.x * blockDim.x + threadIdx.x; g < nf4;
         g += gridDim.x * blockDim.x) {
        int plane = g / HW4;
        int off   = g - plane * HW4;
        int b     = plane / NANCH;
        int a     = plane - b * NANCH;
        int chan  = b * NCH + a * 8 + 4;
        float4 v  = __ldg(p4 + chan * HW4 + off);
        float s;
        s = sig_fast(v.x); acc = fmaf(s, s, acc);
        s = sig_fast(v.y); acc = fmaf(s, s, acc);
        s = sig_fast(v.z); acc = fmaf(s, s, acc);
        s = sig_fast(v.w); acc = fmaf(s, s, acc);
    }

    // Deterministic block reduce
    __shared__ float sh[32];
    int lane = threadIdx.x & 31, w = threadIdx.x >> 5;
    #pragma unroll
    for (int o = 16; o; o >>= 1) acc += __shfl_xor_sync(0xffffffffu, acc, o);
    if (lane == 0) sh[w] = acc;
    __syncthreads();
    if (w == 0) {
        float v = (lane < (CONF_THREADS >> 5)) ? sh[lane] : 0.0f;
        #pragma unroll
        for (int o = 16; o; o >>= 1) v += __shfl_xor_sync(0xffffffffu, v, o);
        if (lane == 0) g_partials[blockIdx.x] = v;
    }
}

// ---------------------------------------------------------------------------
// Kernel 2: single block. Target parse + dedup (last-wins, matching scatter
// .set), sparse gathers for loss_box / loss_cls / conf correction, reduce the
// dense partials, emit the final scalar.
// ---------------------------------------------------------------------------
__global__ void __launch_bounds__(512)
finish_kernel(const float* __restrict__ pred, const float* __restrict__ tg,
              int B, int N, float* __restrict__ out) {
    __shared__ int keys[MAX_TGT];
    __shared__ float shv[4][16];
    __shared__ int shn[16];

    int tid = threadIdx.x;
    int nloc = (N < MAX_TGT) ? N : MAX_TGT;

    // Pass 1: compute scatter keys (b*HW + gy*W + gx), -1 if dropped
    for (int t = tid; t < nloc; t += blockDim.x) {
        const float* r = tg + t * 6;
        int b  = (int)r[0];
        int gx = (int)(r[2] * (float)WID);
        int gy = (int)(r[3] * (float)HGT);
        bool valid = (gx >= 0) & (gx < WID) & (gy >= 0) & (gy < HGT) &
                     (b >= 0) & (b < B);
        keys[t] = valid ? (b * HW + gy * WID + gx) : -1;
    }
    __syncthreads();

    float sbox = 0.0f, scls = 0.0f, scorr = 0.0f;
    int scnt = 0;

    // Pass 2: winners (no later duplicate) gather 24 pred values each
    for (int t = tid; t < nloc; t += blockDim.x) {
        int key = keys[t];
        if (key < 0) continue;
        bool win = true;
        for (int j = t + 1; j < nloc; ++j)
            if (keys[j] == key) { win = false; break; }
        if (!win) continue;

        const float* r = tg + t * 6;
        int b = (int)r[0];
        int c = (int)r[1];
        float tx = r[2], ty = r[3], tw = r[4], th = r[5];
        int cell = key - b * HW;
        int gy = cell / WID;
        int gx = cell - gy * WID;

        #pragma unroll
        for (int a = 0; a < NANCH; ++a) {
            int base = ((b * NCH + a * 8) * HGT + gy) * WID + gx;
            float p[8];
            #pragma unroll
            for (int ch = 0; ch < 8; ++ch)
                p[ch] = __ldg(pred + base + ch * HW);

            float sx = 1.0f / (1.0f + expf(-p[0]));
            float sy = 1.0f / (1.0f + expf(-p[1]));
            float ew = expf(p[2]);
            float eh = expf(p[3]);
            sbox += (sx - tx) * (sx - tx) + (sy - ty) * (sy - ty) +
                    (ew - tw) * (ew - tw) + (eh - th) * (eh - th);

            float s4 = 1.0f / (1.0f + expf(-p[4]));
            scorr += 1.0f - 2.0f * s4;   // (s-1)^2 - s^2 correction

            #pragma unroll
            for (int cc = 0; cc < NCLS; ++cc) {
                float s  = 1.0f / (1.0f + expf(-p[5 + cc]));
                float tt = (cc == c) ? 1.0f : 0.0f;
                scls += (s - tt) * (s - tt);
            }
        }
        scnt += NANCH;
    }

    // Reduce dense conf partials (fixed order: deterministic)
    float sconf = 0.0f;
    for (int i = tid; i < CONF_BLOCKS; i += blockDim.x) sconf += g_partials[i];

    // Block reduce the five accumulators
    int lane = tid & 31, w = tid >> 5;
    #pragma unroll
    for (int o = 16; o; o >>= 1) {
        sbox  += __shfl_xor_sync(0xffffffffu, sbox, o);
        scls  += __shfl_xor_sync(0xffffffffu, scls, o);
        scorr += __shfl_xor_sync(0xffffffffu, scorr, o);
        sconf += __shfl_xor_sync(0xffffffffu, sconf, o);
        scnt  += __shfl_xor_sync(0xffffffffu, scnt, o);
    }
    if (lane == 0) {
        shv[0][w] = sbox; shv[1][w] = scls; shv[2][w] = scorr;
        shv[3][w] = sconf; shn[w] = scnt;
    }
    __syncthreads();
    if (tid == 0) {
        float tb = 0, tc = 0, tr = 0, tf = 0; int tn = 0;
        #pragma unroll
        for (int i = 0; i < 16; ++i) {
            tb += shv[0][i]; tc += shv[1][i]; tr += shv[2][i];
            tf += shv[3][i]; tn += shn[i];
        }
        float n = (float)tn;
        float loss_box  = tb / (n * 4.0f);
        float loss_cls  = tc / (n * (float)NCLS);
        float total     = (float)B * (float)NANCH * (float)HW;
        float loss_conf = (tf + tr) / total;
        out[0] = 5.0f * loss_box + loss_conf + loss_cls;
    }
}

extern "C" void kernel_launch(void* const* d_in, const int* in_sizes, int n_in,
                              void* d_out, int out_size) {
    const float* pred    = (const float*)d_in[0];
    const float* targets = (const float*)d_in[1];
    int B = in_sizes[0] / (NCH * HW);   // 32
    int N = in_sizes[1] / 6;            // 512
    float* out = (float*)d_out;

    conf_kernel<<<CONF_BLOCKS, CONF_THREADS>>>(pred, B * NANCH);
    finish_kernel<<<1, 512>>>(pred, targets, B, N, out);
}

// round 3
// speedup vs baseline: 3.6054x; 3.6054x over previous
#include <cuda_runtime.h>

// Problem constants (fixed-shape: pred (B,24,160,160), targets (N,6))
#define HGT   160
#define WID   160
#define HW    (HGT * WID)          // 25600
#define HW4   (HW / 4)             // 6400 float4 per plane
#define NANCH 3
#define NCLS  3
#define NCH   (NANCH * 8)          // 24 channels

#define CONF_BLOCKS  608
#define CONF_THREADS 256
#define MAX_TGT      2048
#define SP_THREADS   128
#define SP_BLOCKS    12            // 512 targets * 3 anchors / 128

// Scratch (device globals: no allocations allowed). Overwritten every call.
__device__ float g_partials[CONF_BLOCKS];
__device__ float g_sparse[SP_BLOCKS][4];   // {sbox, scls, scorr, count}

__device__ __forceinline__ float sig_fast(float x) {
    return 1.0f / (1.0f + __expf(-x));
}

// ---------------------------------------------------------------------------
// K1: dense pass over ONLY the conf channels (chan = b*24 + a*8 + 4).
// Sum of sigmoid(x)^2 over all B*A*H*W conf elements.
// ---------------------------------------------------------------------------
__global__ void __launch_bounds__(CONF_THREADS)
conf_kernel(const float* __restrict__ pred, int nplanes /* B*A */) {
    const int nf4 = nplanes * HW4;
    float acc = 0.0f;
    const float4* __restrict__ p4 = (const float4*)pred;

    for (int g = blockIdx.x * blockDim.x + threadIdx.x; g < nf4;
         g += gridDim.x * blockDim.x) {
        int plane = g / HW4;
        int off   = g - plane * HW4;
        int b     = plane / NANCH;
        int a     = plane - b * NANCH;
        int chan  = b * NCH + a * 8 + 4;
        float4 v  = __ldg(p4 + chan * HW4 + off);
        float s;
        s = sig_fast(v.x); acc = fmaf(s, s, acc);
        s = sig_fast(v.y); acc = fmaf(s, s, acc);
        s = sig_fast(v.z); acc = fmaf(s, s, acc);
        s = sig_fast(v.w); acc = fmaf(s, s, acc);
    }

    __shared__ float sh[32];
    int lane = threadIdx.x & 31, w = threadIdx.x >> 5;
    #pragma unroll
    for (int o = 16; o; o >>= 1) acc += __shfl_xor_sync(0xffffffffu, acc, o);
    if (lane == 0) sh[w] = acc;
    __syncthreads();
    if (w == 0) {
        float v = (lane < (CONF_THREADS >> 5)) ? sh[lane] : 0.0f;
        #pragma unroll
        for (int o = 16; o; o >>= 1) v += __shfl_xor_sync(0xffffffffu, v, o);
        if (lane == 0) g_partials[blockIdx.x] = v;
    }
}

// ---------------------------------------------------------------------------
// K2: sparse gather, one thread per (target, anchor) task, 12 blocks so the
// scattered DRAM-cold line fetches spread across SMs with high MLP.
// Each block recomputes all keys (targets are tiny / L2-hot) and checks
// last-wins dedup only for its own tasks.
// ---------------------------------------------------------------------------
__global__ void __launch_bounds__(SP_THREADS)
sparse_kernel(const float* __restrict__ pred, const float* __restrict__ tg,
              int B, int N) {
    __shared__ int keys[MAX_TGT];
    int tid  = threadIdx.x;
    int nloc = (N < MAX_TGT) ? N : MAX_TGT;

    // Cooperative key computation for ALL targets
    for (int t = tid; t < nloc; t += SP_THREADS) {
        const float* r = tg + t * 6;
        int b  = (int)r[0];
        int gx = (int)(r[2] * (float)WID);
        int gy = (int)(r[3] * (float)HGT);
        bool valid = (gx >= 0) & (gx < WID) & (gy >= 0) & (gy < HGT) &
                     (b >= 0) & (b < B);
        keys[t] = valid ? (b * HW + gy * WID + gx) : -1;
    }
    __syncthreads();

    float sbox = 0.0f, scls = 0.0f, scorr = 0.0f;
    int   scnt = 0;

    int task = blockIdx.x * SP_THREADS + tid;   // 0 .. N*NANCH-1
    int ntask = nloc * NANCH;
    if (task < ntask) {
        int t = task / NANCH;
        int a = task - t * NANCH;
        int key = keys[t];
        if (key >= 0) {
            bool win = true;
            for (int j = t + 1; j < nloc; ++j)
                if (keys[j] == key) { win = false; break; }
            if (win) {
                const float* r = tg + t * 6;
                int b = (int)r[0];
                int c = (int)r[1];
                float tx = r[2], ty = r[3], tw = r[4], th = r[5];
                int cell = key - b * HW;

                int base = (b * NCH + a * 8) * HW + cell;
                float p[8];
                #pragma unroll
                for (int ch = 0; ch < 8; ++ch)
                    p[ch] = __ldg(pred + base + ch * HW);

                float sx = sig_fast(p[0]);
                float sy = sig_fast(p[1]);
                float ew = __expf(p[2]);
                float eh = __expf(p[3]);
                sbox = (sx - tx) * (sx - tx) + (sy - ty) * (sy - ty) +
                       (ew - tw) * (ew - tw) + (eh - th) * (eh - th);

                scorr = 1.0f - 2.0f * sig_fast(p[4]);   // (s-1)^2 - s^2

                #pragma unroll
                for (int cc = 0; cc < NCLS; ++cc) {
                    float s  = sig_fast(p[5 + cc]);
                    float tt = (cc == c) ? 1.0f : 0.0f;
                    scls += (s - tt) * (s - tt);
                }
                scnt = 1;
            }
        }
    }

    // Deterministic block reduce
    __shared__ float shv[3][4];
    __shared__ int   shn[4];
    int lane = tid & 31, w = tid >> 5;
    #pragma unroll
    for (int o = 16; o; o >>= 1) {
        sbox  += __shfl_xor_sync(0xffffffffu, sbox, o);
        scls  += __shfl_xor_sync(0xffffffffu, scls, o);
        scorr += __shfl_xor_sync(0xffffffffu, scorr, o);
        scnt  += __shfl_xor_sync(0xffffffffu, scnt, o);
    }
    if (lane == 0) { shv[0][w] = sbox; shv[1][w] = scls; shv[2][w] = scorr; shn[w] = scnt; }
    __syncthreads();
    if (tid == 0) {
        float tb = 0, tc = 0, tr = 0; int tn = 0;
        #pragma unroll
        for (int i = 0; i < 4; ++i) {
            tb += shv[0][i]; tc += shv[1][i]; tr += shv[2][i]; tn += shn[i];
        }
        g_sparse[blockIdx.x][0] = tb;
        g_sparse[blockIdx.x][1] = tc;
        g_sparse[blockIdx.x][2] = tr;
        g_sparse[blockIdx.x][3] = (float)tn;
    }
}

// ---------------------------------------------------------------------------
// K3: fold partials into the final scalar. One small block, fixed order.
// ---------------------------------------------------------------------------
__global__ void __launch_bounds__(256)
final_kernel(int B, float* __restrict__ out) {
    __shared__ float sh[8];
    int tid = threadIdx.x;

    float sconf = 0.0f;
    for (int i = tid; i < CONF_BLOCKS; i += 256) sconf += g_partials[i];

    int lane = tid & 31, w = tid >> 5;
    #pragma unroll
    for (int o = 16; o; o >>= 1) sconf += __shfl_xor_sync(0xffffffffu, sconf, o);
    if (lane == 0) sh[w] = sconf;
    __syncthreads();

    if (tid == 0) {
        float tf = 0.0f;
        #pragma unroll
        for (int i = 0; i < 8; ++i) tf += sh[i];

        float tb = 0, tc = 0, tr = 0, tn = 0;
        #pragma unroll
        for (int i = 0; i < SP_BLOCKS; ++i) {
            tb += g_sparse[i][0];
            tc += g_sparse[i][1];
            tr += g_sparse[i][2];
            tn += g_sparse[i][3];
        }
        float loss_box  = tb / (tn * 4.0f);
        float loss_cls  = tc / (tn * (float)NCLS);
        float total     = (float)B * (float)NANCH * (float)HW;
        float loss_conf = (tf + tr) / total;
        out[0] = 5.0f * loss_box + loss_conf + loss_cls;
    }
}

extern "C" void kernel_launch(void* const* d_in, const int* in_sizes, int n_in,
                              void* d_out, int out_size) {
    const float* pred    = (const float*)d_in[0];
    const float* targets = (const float*)d_in[1];
    int B = in_sizes[0] / (NCH * HW);   // 32
    int N = in_sizes[1] / 6;            // 512
    float* out = (float*)d_out;

    conf_kernel<<<CONF_BLOCKS, CONF_THREADS>>>(pred, B * NANCH);
    sparse_kernel<<<SP_BLOCKS, SP_THREADS>>>(pred, targets, B, N);
    final_kernel<<<1, 256>>>(B, out);
}

// round 7
// speedup vs baseline: 5.8242x; 1.6154x over previous
#include <cuda_runtime.h>

// Problem constants (fixed-shape: pred (B,24,160,160), targets (N,6))
#define HGT   160
#define WID   160
#define HW    (HGT * WID)          // 25600
#define HW4   (HW / 4)             // 6400 float4 per plane
#define NANCH 3
#define NCLS  3
#define NCH   (NANCH * 8)          // 24 channels

#define CONF_BX      25            // 6400 f4 / 256 threads
#define CONF_THREADS 256
#define NPLANES      96            // B * NANCH (B=32)
#define CONF_PARTS   (CONF_BX * NPLANES)   // 2400

#define MAX_TGT      2048
#define SP_THREADS   128
#define MAX_SP_BLOCKS 512

// Scratch (device globals: no allocations allowed). Overwritten every call.
__device__ float g_partials[CONF_PARTS];
__device__ float g_sparse[MAX_SP_BLOCKS][4];   // {sbox, scls, scorr, count}

__device__ __forceinline__ float sig_fast(float x) {
    return 1.0f / (1.0f + __expf(-x));
}

// ---------------------------------------------------------------------------
// K1: dense conf pass. Grid (CONF_BX, B*A). Each thread: exactly ONE float4
// load (max MLP, full occupancy) + 4 fast sigmoids + block reduce.
// ---------------------------------------------------------------------------
__global__ void __launch_bounds__(CONF_THREADS)
conf_kernel(const float* __restrict__ pred) {
    int plane = blockIdx.y;                 // b*NANCH + a
    int b = plane / NANCH;
    int a = plane - b * NANCH;
    int chan = b * NCH + a * 8 + 4;
    int off4 = blockIdx.x * CONF_THREADS + threadIdx.x;   // < 6400

    const float4* __restrict__ p4 = (const float4*)pred;
    float4 v = __ldg(p4 + chan * HW4 + off4);

    float s, acc;
    s = sig_fast(v.x); acc = s * s;
    s = sig_fast(v.y); acc = fmaf(s, s, acc);
    s = sig_fast(v.z); acc = fmaf(s, s, acc);
    s = sig_fast(v.w); acc = fmaf(s, s, acc);

    __shared__ float sh[8];
    int lane = threadIdx.x & 31, w = threadIdx.x >> 5;
    #pragma unroll
    for (int o = 16; o; o >>= 1) acc += __shfl_xor_sync(0xffffffffu, acc, o);
    if (lane == 0) sh[w] = acc;
    __syncthreads();
    if (w == 0) {
        float t = (lane < 8) ? sh[lane] : 0.0f;
        #pragma unroll
        for (int o = 4; o; o >>= 1) t += __shfl_xor_sync(0xffffffffu, t, o);
        if (lane == 0) g_partials[blockIdx.y * CONF_BX + blockIdx.x] = t;
    }
}

// ---------------------------------------------------------------------------
// K2: sparse pass. ONE thread per (target, anchor, channel) -> one scattered
// LDG per thread, spread over ~96 SMs => a single DRAM latency round.
// Dedup (last-wins scatter semantics) via int4-vectorized shared-key scan.
// ---------------------------------------------------------------------------
__global__ void __launch_bounds__(SP_THREADS)
sparse_kernel(const float* __restrict__ pred, const float* __restrict__ tg,
              int B, int N) {
    __shared__ int keys[MAX_TGT];
    int tid  = threadIdx.x;
    int nloc = (N < MAX_TGT) ? N : MAX_TGT;

    // Cooperative key computation for ALL targets (tiny, L2-hot)
    for (int t = tid; t < nloc; t += SP_THREADS) {
        const float* r = tg + t * 6;
        int b  = (int)r[0];
        int gx = (int)(r[2] * (float)WID);
        int gy = (int)(r[3] * (float)HGT);
        bool valid = (gx >= 0) & (gx < WID) & (gy >= 0) & (gy < HGT) &
                     (b >= 0) & (b < B);
        keys[t] = valid ? (b * HW + gy * WID + gx) : -1;
    }
    __syncthreads();

    float sbox = 0.0f, scls = 0.0f, scorr = 0.0f;
    int   scnt = 0;

    int task2 = blockIdx.x * SP_THREADS + tid;   // (t, a, ch) flattened
    int ntask2 = nloc * NANCH * 8;
    if (task2 < ntask2) {
        int ch   = task2 & 7;
        int task = task2 >> 3;
        int t = task / NANCH;
        int a = task - t * NANCH;
        int key = keys[t];
        if (key >= 0) {
            // last-wins: thread's target survives iff no later j has same key
            bool win = true;
            const int4* k4 = (const int4*)keys;
            int q0 = (t + 1) >> 2;
            int q1 = (nloc + 3) >> 2;
            for (int q = q0; q < q1; ++q) {
                int4 kk = k4[q];
                int j = q * 4;
                win &= !(((kk.x == key) & (j     > t) & (j     < nloc)) |
                         ((kk.y == key) & (j + 1 > t) & (j + 1 < nloc)) |
                         ((kk.z == key) & (j + 2 > t) & (j + 2 < nloc)) |
                         ((kk.w == key) & (j + 3 > t) & (j + 3 < nloc)));
            }
            if (win) {
                const float* r = tg + t * 6;
                int b = (int)r[0];
                int c = (int)r[1];
                int cell = key - b * HW;

                float p = __ldg(pred + (b * NCH + a * 8 + ch) * HW + cell);

                if (ch < 2) {
                    float s = sig_fast(p);
                    float d = s - r[2 + ch];            // tx / ty
                    sbox = d * d;
                } else if (ch < 4) {
                    float e = __expf(p);
                    float d = e - r[2 + ch];            // tw / th
                    sbox = d * d;
                } else if (ch == 4) {
                    scorr = 1.0f - 2.0f * sig_fast(p);  // (s-1)^2 - s^2
                    scnt  = 1;                          // one per (t, a)
                } else {
                    float s  = sig_fast(p);
                    float tt = ((ch - 5) == c) ? 1.0f : 0.0f;
                    float d  = s - tt;
                    scls = d * d;
                }
            }
        }
    }

    // Deterministic block reduce
    __shared__ float shv[3][4];
    __shared__ int   shn[4];
    int lane = tid & 31, w = tid >> 5;
    #pragma unroll
    for (int o = 16; o; o >>= 1) {
        sbox  += __shfl_xor_sync(0xffffffffu, sbox, o);
        scls  += __shfl_xor_sync(0xffffffffu, scls, o);
        scorr += __shfl_xor_sync(0xffffffffu, scorr, o);
        scnt  += __shfl_xor_sync(0xffffffffu, scnt, o);
    }
    if (lane == 0) { shv[0][w] = sbox; shv[1][w] = scls; shv[2][w] = scorr; shn[w] = scnt; }
    __syncthreads();
    if (tid == 0) {
        float tb = 0, tc = 0, tr = 0; int tn = 0;
        #pragma unroll
        for (int i = 0; i < 4; ++i) {
            tb += shv[0][i]; tc += shv[1][i]; tr += shv[2][i]; tn += shn[i];
        }
        g_sparse[blockIdx.x][0] = tb;
        g_sparse[blockIdx.x][1] = tc;
        g_sparse[blockIdx.x][2] = tr;
        g_sparse[blockIdx.x][3] = (float)tn;
    }
}

// ---------------------------------------------------------------------------
// K3: fold partials into the final scalar. One block, fixed order.
// ---------------------------------------------------------------------------
__global__ void __launch_bounds__(256)
final_kernel(int B, int nspb, float* __restrict__ out) {
    __shared__ float sh[8];
    int tid = threadIdx.x;

    float sconf = 0.0f;
    for (int i = tid; i < CONF_PARTS; i += 256) sconf += g_partials[i];

    int lane = tid & 31, w = tid >> 5;
    #pragma unroll
    for (int o = 16; o; o >>= 1) sconf += __shfl_xor_sync(0xffffffffu, sconf, o);
    if (lane == 0) sh[w] = sconf;
    __syncthreads();

    if (tid == 0) {
        float tf = 0.0f;
        #pragma unroll
        for (int i = 0; i < 8; ++i) tf += sh[i];

        float tb = 0, tc = 0, tr = 0, tn = 0;
        for (int i = 0; i < nspb; ++i) {
            tb += g_sparse[i][0];
            tc += g_sparse[i][1];
            tr += g_sparse[i][2];
            tn += g_sparse[i][3];
        }
        float loss_box  = tb / (tn * 4.0f);
        float loss_cls  = tc / (tn * (float)NCLS);
        float total     = (float)B * (float)NANCH * (float)HW;
        float loss_conf = (tf + tr) / total;
        out[0] = 5.0f * loss_box + loss_conf + loss_cls;
    }
}

extern "C" void kernel_launch(void* const* d_in, const int* in_sizes, int n_in,
                              void* d_out, int out_size) {
    const float* pred    = (const float*)d_in[0];
    const float* targets = (const float*)d_in[1];
    int B = in_sizes[0] / (NCH * HW);   // 32
    int N = in_sizes[1] / 6;            // 512
    float* out = (float*)d_out;

    int ntask2 = N * NANCH * 8;
    int nspb = (ntask2 + SP_THREADS - 1) / SP_THREADS;   // 96 for N=512
    if (nspb > MAX_SP_BLOCKS) nspb = MAX_SP_BLOCKS;      // (N fixed at 512)

    dim3 cgrid(CONF_BX, NPLANES);
    conf_kernel<<<cgrid, CONF_THREADS>>>(pred);
    sparse_kernel<<<nspb, SP_THREADS>>>(pred, targets, B, N);
    final_kernel<<<1, 256>>>(B, nspb, out);
}

// round 8
// speedup vs baseline: 9.1183x; 1.5656x over previous
#include <cuda_runtime.h>

// Fixed-shape problem: pred (B=32, 24, 160, 160) fp32, targets (N=512, 6)
#define HGT   160
#define WID   160
#define HW    (HGT * WID)            // 25600
#define HW4   (HW / 4)               // 6400 float4 per plane
#define NANCH 3
#define NCLS  3
#define NCH   (NANCH * 8)

#define NTHREADS   256
#define CONF_BPP   5                 // blocks per plane (5*256 f4 = 6400)
#define NPLANES    96                // B * NANCH
#define NCONF      (CONF_BPP * NPLANES)   // 480
#define SEG_F4     (NTHREADS)        // f4 per segment step
#define MAX_TGT    2048
#define MAX_SPB    64

// Scratch (device globals; no allocation allowed). Overwritten every call.
__device__ float g_partials[NCONF];
__device__ float g_sparse[MAX_SPB][4];   // {sbox, scls, scorr, count}
__device__ int   g_count = 0;            // reset by the fold block each launch

__device__ __forceinline__ float tanh_fast(float x) {
    float r;
    asm("tanh.approx.f32 %0, %1;" : "=f"(r) : "f"(x));
    return r;
}
// sigmoid(x) = 0.5*tanh(0.5x) + 0.5   (one MUFU op)
__device__ __forceinline__ float sig_fast(float x) {
    return fmaf(0.5f, tanh_fast(0.5f * x), 0.5f);
}

__global__ void __launch_bounds__(NTHREADS)
fused_kernel(const float* __restrict__ pred, const float* __restrict__ tg,
             int B, int N, int nspb, int nblocks, float* __restrict__ out) {
    __shared__ int   keys[MAX_TGT];     // used by sparse blocks only
    __shared__ float shf[8];
    __shared__ float shv[3][8];
    __shared__ int   shn[8];
    __shared__ int   s_ticket;

    const int tid  = threadIdx.x;
    const int bid  = blockIdx.x;
    const int lane = tid & 31, w = tid >> 5;

    if (bid < NCONF) {
        // ---------------- conf block: 5 float4 from one plane ----------------
        int plane = bid / CONF_BPP;          // b*NANCH + a
        int seg   = bid - plane * CONF_BPP;
        int b     = plane / NANCH;
        int a     = plane - b * NANCH;
        int chan  = b * NCH + a * 8 + 4;
        const float4* __restrict__ p4 = (const float4*)pred + chan * HW4
                                        + seg * (CONF_BPP * SEG_F4 / CONF_BPP) * CONF_BPP; // seg*1280
        // (seg * 1280) written explicitly:
        p4 = (const float4*)pred + chan * HW4 + seg * (SEG_F4 * CONF_BPP) + tid;

        float4 v0 = __ldg(p4);
        float4 v1 = __ldg(p4 + SEG_F4);
        float4 v2 = __ldg(p4 + 2 * SEG_F4);
        float4 v3 = __ldg(p4 + 3 * SEG_F4);
        float4 v4 = __ldg(p4 + 4 * SEG_F4);

        float acc = 0.0f, s;
        #define SACC(x) { s = sig_fast(x); acc = fmaf(s, s, acc); }
        SACC(v0.x) SACC(v0.y) SACC(v0.z) SACC(v0.w)
        SACC(v1.x) SACC(v1.y) SACC(v1.z) SACC(v1.w)
        SACC(v2.x) SACC(v2.y) SACC(v2.z) SACC(v2.w)
        SACC(v3.x) SACC(v3.y) SACC(v3.z) SACC(v3.w)
        SACC(v4.x) SACC(v4.y) SACC(v4.z) SACC(v4.w)
        #undef SACC

        #pragma unroll
        for (int o = 16; o; o >>= 1) acc += __shfl_xor_sync(0xffffffffu, acc, o);
        if (lane == 0) shf[w] = acc;
        __syncthreads();
        if (tid == 0) {
            float t = 0.0f;
            #pragma unroll
            for (int i = 0; i < 8; ++i) t += shf[i];
            g_partials[bid] = t;
        }
    } else {
        // ---------------- sparse block: 1 thread per (t, a, ch) --------------
        int nloc = (N < MAX_TGT) ? N : MAX_TGT;
        for (int t = tid; t < nloc; t += NTHREADS) {
            const float* r = tg + t * 6;
            int b  = (int)r[0];
            int gx = (int)(r[2] * (float)WID);
            int gy = (int)(r[3] * (float)HGT);
            bool valid = (gx >= 0) & (gx < WID) & (gy >= 0) & (gy < HGT) &
                         (b >= 0) & (b < B);
            keys[t] = valid ? (b * HW + gy * WID + gx) : -1;
        }
        __syncthreads();

        float sbox = 0.0f, scls = 0.0f, scorr = 0.0f;
        int   scnt = 0;

        int task2  = (bid - NCONF) * NTHREADS + tid;    // (t, a, ch)
        int ntask2 = nloc * NANCH * 8;
        if (task2 < ntask2) {
            int ch   = task2 & 7;
            int task = task2 >> 3;
            int t = task / NANCH;
            int a = task - t * NANCH;
            int key = keys[t];
            if (key >= 0) {
                // last-wins dedup: survive iff no later j shares the key
                bool win = true;
                const int4* k4 = (const int4*)keys;
                int q1 = (nloc + 3) >> 2;
                for (int q = (t + 1) >> 2; q < q1; ++q) {
                    int4 kk = k4[q];
                    int j = q * 4;
                    win &= !(((kk.x == key) & (j     > t) & (j     < nloc)) |
                             ((kk.y == key) & (j + 1 > t) & (j + 1 < nloc)) |
                             ((kk.z == key) & (j + 2 > t) & (j + 2 < nloc)) |
                             ((kk.w == key) & (j + 3 > t) & (j + 3 < nloc)));
                }
                if (win) {
                    const float* r = tg + t * 6;
                    int b = (int)r[0];
                    int c = (int)r[1];
                    int cell = key - b * HW;
                    float p = __ldg(pred + (b * NCH + a * 8 + ch) * HW + cell);

                    if (ch < 2) {
                        float d = sig_fast(p) - r[2 + ch];
                        sbox = d * d;
                    } else if (ch < 4) {
                        float d = __expf(p) - r[2 + ch];
                        sbox = d * d;
                    } else if (ch == 4) {
                        scorr = 1.0f - 2.0f * sig_fast(p);  // (s-1)^2 - s^2
                        scnt  = 1;
                    } else {
                        float tt = ((ch - 5) == c) ? 1.0f : 0.0f;
                        float d  = sig_fast(p) - tt;
                        scls = d * d;
                    }
                }
            }
        }

        #pragma unroll
        for (int o = 16; o; o >>= 1) {
            sbox  += __shfl_xor_sync(0xffffffffu, sbox, o);
            scls  += __shfl_xor_sync(0xffffffffu, scls, o);
            scorr += __shfl_xor_sync(0xffffffffu, scorr, o);
            scnt  += __shfl_xor_sync(0xffffffffu, scnt, o);
        }
        if (lane == 0) { shv[0][w] = sbox; shv[1][w] = scls; shv[2][w] = scorr; shn[w] = scnt; }
        __syncthreads();
        if (tid == 0) {
            float tb = 0, tc = 0, tr = 0; int tn = 0;
            #pragma unroll
            for (int i = 0; i < 8; ++i) {
                tb += shv[0][i]; tc += shv[1][i]; tr += shv[2][i]; tn += shn[i];
            }
            int sb = bid - NCONF;
            g_sparse[sb][0] = tb;
            g_sparse[sb][1] = tc;
            g_sparse[sb][2] = tr;
            g_sparse[sb][3] = (float)tn;
        }
    }

    // ---------------- last-arriving block folds everything -------------------
    __threadfence();
    if (tid == 0) s_ticket = atomicAdd(&g_count, 1);
    __syncthreads();
    if (s_ticket != nblocks - 1) return;

    // All partials are globally visible (threadfence before the final ticket).
    float sconf = 0.0f;
    for (int i = tid; i < NCONF; i += NTHREADS)
        sconf += *(volatile float*)&g_partials[i];

    #pragma unroll
    for (int o = 16; o; o >>= 1) sconf += __shfl_xor_sync(0xffffffffu, sconf, o);
    __syncthreads();   // reuse shf safely
    if (lane == 0) shf[w] = sconf;
    __syncthreads();

    if (tid == 0) {
        float tf = 0.0f;
        #pragma unroll
        for (int i = 0; i < 8; ++i) tf += shf[i];

        float tb = 0, tc = 0, tr = 0, tn = 0;
        for (int i = 0; i < nspb; ++i) {
            tb += *(volatile float*)&g_sparse[i][0];
            tc += *(volatile float*)&g_sparse[i][1];
            tr += *(volatile float*)&g_sparse[i][2];
            tn += *(volatile float*)&g_sparse[i][3];
        }
        float loss_box  = tb / (tn * 4.0f);
        float loss_cls  = tc / (tn * (float)NCLS);
        float total     = (float)B * (float)NANCH * (float)HW;
        float loss_conf = (tf + tr) / total;
        out[0] = 5.0f * loss_box + loss_conf + loss_cls;
        g_count = 0;   // reset for next graph replay
    }
}

extern "C" void kernel_launch(void* const* d_in, const int* in_sizes, int n_in,
                              void* d_out, int out_size) {
    const float* pred    = (const float*)d_in[0];
    const float* targets = (const float*)d_in[1];
    int B = in_sizes[0] / (NCH * HW);   // 32
    int N = in_sizes[1] / 6;            // 512
    float* out = (float*)d_out;

    int ntask2 = N * NANCH * 8;                       // 12288
    int nspb = (ntask2 + NTHREADS - 1) / NTHREADS;    // 48
    if (nspb > MAX_SPB) nspb = MAX_SPB;
    int nblocks = NCONF + nspb;                       // 528

    fused_kernel<<<nblocks, NTHREADS>>>(pred, targets, B, N, nspb, nblocks, out);
}

// round 10
// speedup vs baseline: 12.6190x; 1.3839x over previous
#include <cuda_runtime.h>

// Fixed-shape problem: pred (B=32, 24, 160, 160) fp32, targets (N=512, 6)
#define HGT   160
#define WID   160
#define HW    (HGT * WID)            // 25600
#define HW4   (HW / 4)               // 6400 float4 per plane
#define NANCH 3
#define NCLS  3
#define NCH   (NANCH * 8)

#define NTHREADS   256
#define CONF_BPP   5                 // blocks per plane (5*256 f4 = 6400)
#define NPLANES    96                // B * NANCH
#define NCONF      (CONF_BPP * NPLANES)   // 480
#define SEG_F4     (NTHREADS)
#define MAX_TGT    2048
#define MAX_SPB    64
#define MAX_LOCAL  16                // distinct targets per sparse block (<=12)

// Scratch (device globals; no allocation allowed). Overwritten every call.
__device__ float g_partials[NCONF];
__device__ float g_sparse[MAX_SPB][4];   // {sbox, scls, scorr, count}
__device__ int   g_count = 0;            // reset by fold block each launch

__device__ __forceinline__ float tanh_fast(float x) {
    float r;
    asm("tanh.approx.f32 %0, %1;" : "=f"(r) : "f"(x));
    return r;
}
// sigmoid(x) = 0.5*tanh(0.5x) + 0.5   (one MUFU op)
__device__ __forceinline__ float sig_fast(float x) {
    return fmaf(0.5f, tanh_fast(0.5f * x), 0.5f);
}

__global__ void __launch_bounds__(NTHREADS)
fused_kernel(const float* __restrict__ pred, const float* __restrict__ tg,
             int B, int N, int nspb, int nblocks, float* __restrict__ out) {
    __shared__ int   keys[MAX_TGT];     // sparse blocks only
    __shared__ int   swin[MAX_LOCAL];
    __shared__ float shf[8];
    __shared__ float shv[4][8];
    __shared__ int   s_ticket;

    const int tid  = threadIdx.x;
    const int bid  = blockIdx.x;
    const int lane = tid & 31, w = tid >> 5;

    if (bid < NCONF) {
        // ---------------- conf block: 5 float4 from one plane ----------------
        int plane = bid / CONF_BPP;          // b*NANCH + a
        int seg   = bid - plane * CONF_BPP;
        int b     = plane / NANCH;
        int a     = plane - b * NANCH;
        int chan  = b * NCH + a * 8 + 4;
        const float4* __restrict__ p4 =
            (const float4*)pred + chan * HW4 + seg * (SEG_F4 * CONF_BPP) + tid;

        float4 v0 = __ldg(p4);
        float4 v1 = __ldg(p4 + SEG_F4);
        float4 v2 = __ldg(p4 + 2 * SEG_F4);
        float4 v3 = __ldg(p4 + 3 * SEG_F4);
        float4 v4 = __ldg(p4 + 4 * SEG_F4);

        float acc = 0.0f, s;
        #define SACC(x) { s = sig_fast(x); acc = fmaf(s, s, acc); }
        SACC(v0.x) SACC(v0.y) SACC(v0.z) SACC(v0.w)
        SACC(v1.x) SACC(v1.y) SACC(v1.z) SACC(v1.w)
        SACC(v2.x) SACC(v2.y) SACC(v2.z) SACC(v2.w)
        SACC(v3.x) SACC(v3.y) SACC(v3.z) SACC(v3.w)
        SACC(v4.x) SACC(v4.y) SACC(v4.z) SACC(v4.w)
        #undef SACC

        #pragma unroll
        for (int o = 16; o; o >>= 1) acc += __shfl_xor_sync(0xffffffffu, acc, o);
        if (lane == 0) shf[w] = acc;
        __syncthreads();
        if (tid == 0) {
            float t = 0.0f;
            #pragma unroll
            for (int i = 0; i < 8; ++i) t += shf[i];
            g_partials[bid] = t;
        }
    } else {
        // ---------------- sparse block ---------------------------------------
        int nloc = (N < MAX_TGT) ? N : MAX_TGT;
        int sb   = bid - NCONF;

        // keys for ALL targets (tiny, L2-hot)
        for (int t = tid; t < nloc; t += NTHREADS) {
            const float* r = tg + t * 6;
            int b  = (int)r[0];
            int gx = (int)(r[2] * (float)WID);
            int gy = (int)(r[3] * (float)HGT);
            bool valid = (gx >= 0) & (gx < WID) & (gy >= 0) & (gy < HGT) &
                         (b >= 0) & (b < B);
            keys[t] = valid ? (b * HW + gy * WID + gx) : -1;
        }
        if (tid < MAX_LOCAL) swin[tid] = 1;
        __syncthreads();

        // Distinct target range for this block's 256 (t,a,ch) tasks
        int task_lo = sb * NTHREADS;
        int task_hi = task_lo + NTHREADS - 1;
        int ntask2  = nloc * NANCH * 8;
        if (task_hi >= ntask2) task_hi = ntask2 - 1;
        int t0 = task_lo / (NANCH * 8);
        int t1 = (task_hi >= task_lo) ? task_hi / (NANCH * 8) : t0 - 1;
        int nlocal = t1 - t0 + 1;              // <= 12

        // Cooperative last-wins dedup: items = (target_local, 16-key chunk)
        if (nlocal > 0) {
            int nchunk = (nloc + 15) >> 4;     // 32 for nloc=512
            int nitems = nlocal * nchunk;
            const int4* k4 = (const int4*)keys;
            for (int item = tid; item < nitems; item += NTHREADS) {
                int tl    = item / nchunk;
                int chunk = item - tl * nchunk;
                int t     = t0 + tl;
                int key   = keys[t];
                if (key < 0) continue;
                int jbase = chunk << 4;
                bool hit = false;
                #pragma unroll
                for (int q = 0; q < 4; ++q) {
                    int4 kk = k4[(jbase >> 2) + q];
                    int j = jbase + q * 4;
                    hit |= ((kk.x == key) & (j     > t) & (j     < nloc)) |
                           ((kk.y == key) & (j + 1 > t) & (j + 1 < nloc)) |
                           ((kk.z == key) & (j + 2 > t) & (j + 2 < nloc)) |
                           ((kk.w == key) & (j + 3 > t) & (j + 3 < nloc));
                }
                if (hit) swin[tl] = 0;         // benign race: same value
            }
        }
        __syncthreads();

        float sbox = 0.0f, scls = 0.0f, scorr = 0.0f;
        int   scnt = 0;

        int task2 = task_lo + tid;
        if (task2 < ntask2) {
            int ch   = task2 & 7;
            int task = task2 >> 3;
            int t = task / NANCH;
            int a = task - t * NANCH;
            int key = keys[t];
            if (key >= 0 && swin[t - t0]) {
                const float* r = tg + t * 6;
                int b = (int)r[0];
                int c = (int)r[1];
                int cell = key - b * HW;
                float p = __ldg(pred + (b * NCH + a * 8 + ch) * HW + cell);

                if (ch < 2) {
                    float d = sig_fast(p) - r[2 + ch];
                    sbox = d * d;
                } else if (ch < 4) {
                    float d = __expf(p) - r[2 + ch];
                    sbox = d * d;
                } else if (ch == 4) {
                    scorr = 1.0f - 2.0f * sig_fast(p);  // (s-1)^2 - s^2
                    scnt  = 1;
                } else {
                    float tt = ((ch - 5) == c) ? 1.0f : 0.0f;
                    float d  = sig_fast(p) - tt;
                    scls = d * d;
                }
            }
        }

        float fcnt = (float)scnt;
        #pragma unroll
        for (int o = 16; o; o >>= 1) {
            sbox  += __shfl_xor_sync(0xffffffffu, sbox, o);
            scls  += __shfl_xor_sync(0xffffffffu, scls, o);
            scorr += __shfl_xor_sync(0xffffffffu, scorr, o);
            fcnt  += __shfl_xor_sync(0xffffffffu, fcnt, o);
        }
        if (lane == 0) {
            shv[0][w] = sbox; shv[1][w] = scls; shv[2][w] = scorr; shv[3][w] = fcnt;
        }
        __syncthreads();
        if (tid == 0) {
            float tb = 0, tc = 0, tr = 0, tn = 0;
            #pragma unroll
            for (int i = 0; i < 8; ++i) {
                tb += shv[0][i]; tc += shv[1][i]; tr += shv[2][i]; tn += shv[3][i];
            }
            g_sparse[sb][0] = tb;
            g_sparse[sb][1] = tc;
            g_sparse[sb][2] = tr;
            g_sparse[sb][3] = tn;
        }
    }

    // ---------------- last-arriving block folds everything -------------------
    if (tid == 0) {
        __threadfence();                       // order this block's partial store
        s_ticket = atomicAdd(&g_count, 1);
    }
    __syncthreads();
    if (s_ticket != nblocks - 1) return;
    __threadfence();                           // acquire side

    // conf partials: <=2 per thread, parallel
    float sconf = 0.0f;
    for (int i = tid; i < NCONF; i += NTHREADS)
        sconf += *(volatile float*)&g_partials[i];

    // sparse rows: thread i < nspb owns row i, parallel
    float tb = 0, tc = 0, tr = 0, tn = 0;
    if (tid < nspb) {
        volatile float* rowp = &g_sparse[tid][0];
        tb = rowp[0]; tc = rowp[1]; tr = rowp[2]; tn = rowp[3];
    }

    #pragma unroll
    for (int o = 16; o; o >>= 1) {
        sconf += __shfl_xor_sync(0xffffffffu, sconf, o);
        tb    += __shfl_xor_sync(0xffffffffu, tb, o);
        tc    += __shfl_xor_sync(0xffffffffu, tc, o);
        tr    += __shfl_xor_sync(0xffffffffu, tr, o);
        tn    += __shfl_xor_sync(0xffffffffu, tn, o);
    }
    __syncthreads();                           // shv/shf reuse safe
    if (lane == 0) {
        shf[w] = sconf;
        shv[0][w] = tb; shv[1][w] = tc; shv[2][w] = tr; shv[3][w] = tn;
    }
    __syncthreads();

    if (tid == 0) {
        float tf = 0, b2 = 0, c2 = 0, r2 = 0, n2 = 0;
        #pragma unroll
        for (int i = 0; i < 8; ++i) {
            tf += shf[i];
            b2 += shv[0][i]; c2 += shv[1][i]; r2 += shv[2][i]; n2 += shv[3][i];
        }
        float loss_box  = b2 / (n2 * 4.0f);
        float loss_cls  = c2 / (n2 * (float)NCLS);
        float total     = (float)B * (float)NANCH * (float)HW;
        float loss_conf = (tf + r2) / total;
        out[0] = 5.0f * loss_box + loss_conf + loss_cls;
        g_count = 0;                           // reset for next graph replay
    }
}

extern "C" void kernel_launch(void* const* d_in, const int* in_sizes, int n_in,
                              void* d_out, int out_size) {
    const float* pred    = (const float*)d_in[0];
    const float* targets = (const float*)d_in[1];
    int B = in_sizes[0] / (NCH * HW);   // 32
    int N = in_sizes[1] / 6;            // 512
    float* out = (float*)d_out;

    int ntask2 = N * NANCH * 8;                       // 12288
    int nspb = (ntask2 + NTHREADS - 1) / NTHREADS;    // 48
    if (nspb > MAX_SPB) nspb = MAX_SPB;
    int nblocks = NCONF + nspb;                       // 528

    fused_kernel<<<nblocks, NTHREADS>>>(pred, targets, B, N, nspb, nblocks, out);
}

// round 11
// speedup vs baseline: 15.0890x; 1.1957x over previous
#include <cuda_runtime.h>
#include <cstdint>

// Fixed-shape problem: pred (B=32, 24, 160, 160) fp32, targets (N=512, 6)
#define HGT   160
#define WID   160
#define HW    (HGT * WID)            // 25600
#define NANCH 3
#define NCLS  3
#define NCH   24

#define NTHREADS   256
#define PLANE_B    (HW * 4)          // 102400 bytes per conf plane
#define CHUNK_B    20480             // bulk-copy chunk
#define CHUNK_F4   (CHUNK_B / 16)    // 1280 float4
#define NCHUNKS    5                 // 5 * 20480 = 102400
#define NSTAGE     3
#define SMEM_DYN   (NSTAGE * CHUNK_B)   // 61440 bytes
#define MAX_TGT    2048
#define MAX_SPB    64
#define MAX_LOCAL  16

// Scratch (device globals; no allocation allowed). Overwritten every call.
__device__ float g_partials[NANCH * 64];     // one per conf plane (<=192)
__device__ float g_sparse[MAX_SPB][4];       // {sbox, scls, scorr, count}
__device__ int   g_count = 0;                // reset by fold block each launch

__device__ __forceinline__ float tanh_fast(float x) {
    float r;
    asm("tanh.approx.f32 %0, %1;" : "=f"(r) : "f"(x));
    return r;
}
// sigmoid(x) = 0.5*tanh(0.5x) + 0.5   (one MUFU op)
__device__ __forceinline__ float sig_fast(float x) {
    return fmaf(0.5f, tanh_fast(0.5f * x), 0.5f);
}

__device__ __forceinline__ uint32_t smem_u32(const void* p) {
    return (uint32_t)__cvta_generic_to_shared(p);
}

__device__ __forceinline__ void mbar_init(uint32_t mbar, uint32_t cnt) {
    asm volatile("mbarrier.init.shared.b64 [%0], %1;" :: "r"(mbar), "r"(cnt) : "memory");
}
__device__ __forceinline__ void mbar_expect_tx(uint32_t mbar, uint32_t bytes) {
    asm volatile("mbarrier.arrive.expect_tx.shared.b64 _, [%0], %1;"
                 :: "r"(mbar), "r"(bytes) : "memory");
}
__device__ __forceinline__ void mbar_wait(uint32_t mbar, uint32_t parity) {
    asm volatile(
        "{\n\t"
        ".reg .pred P;\n\t"
        "WAIT_%=:\n\t"
        "mbarrier.try_wait.parity.acquire.cta.shared::cta.b64 P, [%0], %1, 0x989680;\n\t"
        "@P bra.uni DONE_%=;\n\t"
        "bra.uni WAIT_%=;\n\t"
        "DONE_%=:\n\t"
        "}"
        :: "r"(mbar), "r"(parity) : "memory");
}
__device__ __forceinline__ void bulk_g2s(uint32_t dst_smem, const void* src_gmem,
                                         uint32_t bytes, uint32_t mbar) {
    asm volatile(
        "cp.async.bulk.shared::cta.global.mbarrier::complete_tx::bytes "
        "[%0], [%1], %2, [%3];"
        :: "r"(dst_smem), "l"(src_gmem), "r"(bytes), "r"(mbar) : "memory");
}

extern __shared__ float4 dynbuf[];   // conf: 3x20KB stage buffers; sparse: keys

__global__ void __launch_bounds__(NTHREADS)
fused_kernel(const float* __restrict__ pred, const float* __restrict__ tg,
             int B, int N, int nconf, int nspb, int nblocks,
             float* __restrict__ out) {
    __shared__ uint64_t mbar_sto[NSTAGE];
    __shared__ int      swin[MAX_LOCAL];
    __shared__ float    shf[8];
    __shared__ float    shv[4][8];
    __shared__ int      s_ticket;

    const int tid  = threadIdx.x;
    const int bid  = blockIdx.x;
    const int lane = tid & 31, w = tid >> 5;

    if (bid < nconf) {
        // ============ conf block: one plane via cp.async.bulk pipeline =======
        int b = bid / NANCH;
        int a = bid - b * NANCH;
        const char* gsrc = (const char*)pred +
                           (size_t)(b * NCH + a * 8 + 4) * PLANE_B / 1 * 1;
        gsrc = (const char*)pred + (size_t)(b * NCH + a * 8 + 4) * (size_t)PLANE_B;

        uint32_t sbase = smem_u32(dynbuf);
        uint32_t mb0   = smem_u32(&mbar_sto[0]);

        if (tid == 0) {
            #pragma unroll
            for (int s = 0; s < NSTAGE; ++s) mbar_init(mb0 + 8 * s, 1);
        }
        __syncthreads();

        if (tid == 0) {
            #pragma unroll
            for (int s = 0; s < NSTAGE; ++s) {
                mbar_expect_tx(mb0 + 8 * s, CHUNK_B);
                bulk_g2s(sbase + s * CHUNK_B, gsrc + s * CHUNK_B, CHUNK_B,
                         mb0 + 8 * s);
            }
        }

        float acc = 0.0f;
        #pragma unroll
        for (int c = 0; c < NCHUNKS; ++c) {
            int s = c % NSTAGE;
            mbar_wait(mb0 + 8 * s, (c / NSTAGE) & 1);

            const float4* buf = dynbuf + s * CHUNK_F4 + tid;
            float4 v0 = buf[0];
            float4 v1 = buf[256];
            float4 v2 = buf[512];
            float4 v3 = buf[768];
            float4 v4 = buf[1024];
            float sg;
            #define SACC(x) { sg = sig_fast(x); acc = fmaf(sg, sg, acc); }
            SACC(v0.x) SACC(v0.y) SACC(v0.z) SACC(v0.w)
            SACC(v1.x) SACC(v1.y) SACC(v1.z) SACC(v1.w)
            SACC(v2.x) SACC(v2.y) SACC(v2.z) SACC(v2.w)
            SACC(v3.x) SACC(v3.y) SACC(v3.z) SACC(v3.w)
            SACC(v4.x) SACC(v4.y) SACC(v4.z) SACC(v4.w)
            #undef SACC

            if (c + NSTAGE < NCHUNKS) {
                __syncthreads();   // all reads of stage s done before refill
                if (tid == 0) {
                    mbar_expect_tx(mb0 + 8 * s, CHUNK_B);
                    bulk_g2s(sbase + s * CHUNK_B, gsrc + (c + NSTAGE) * CHUNK_B,
                             CHUNK_B, mb0 + 8 * s);
                }
            }
        }

        #pragma unroll
        for (int o = 16; o; o >>= 1) acc += __shfl_xor_sync(0xffffffffu, acc, o);
        if (lane == 0) shf[w] = acc;
        __syncthreads();
        if (tid == 0) {
            float t = 0.0f;
            #pragma unroll
            for (int i = 0; i < 8; ++i) t += shf[i];
            g_partials[bid] = t;
        }
    } else {
        // ============ sparse block (cooperative dedup, 1 thread/(t,a,ch)) ====
        int* keys = (int*)dynbuf;
        int nloc = (N < MAX_TGT) ? N : MAX_TGT;
        int sb   = bid - nconf;

        for (int t = tid; t < nloc; t += NTHREADS) {
            const float* r = tg + t * 6;
            int b  = (int)r[0];
            int gx = (int)(r[2] * (float)WID);
            int gy = (int)(r[3] * (float)HGT);
            bool valid = (gx >= 0) & (gx < WID) & (gy >= 0) & (gy < HGT) &
                         (b >= 0) & (b < B);
            keys[t] = valid ? (b * HW + gy * WID + gx) : -1;
        }
        if (tid < MAX_LOCAL) swin[tid] = 1;
        __syncthreads();

        int task_lo = sb * NTHREADS;
        int task_hi = task_lo + NTHREADS - 1;
        int ntask2  = nloc * NANCH * 8;
        if (task_hi >= ntask2) task_hi = ntask2 - 1;
        int t0 = task_lo / (NANCH * 8);
        int t1 = (task_hi >= task_lo) ? task_hi / (NANCH * 8) : t0 - 1;
        int nlocal = t1 - t0 + 1;

        if (nlocal > 0) {
            int nchunk = (nloc + 15) >> 4;
            int nitems = nlocal * nchunk;
            const int4* k4 = (const int4*)keys;
            for (int item = tid; item < nitems; item += NTHREADS) {
                int tl    = item / nchunk;
                int chunk = item - tl * nchunk;
                int t     = t0 + tl;
                int key   = keys[t];
                if (key < 0) continue;
                int jbase = chunk << 4;
                bool hit = false;
                #pragma unroll
                for (int q = 0; q < 4; ++q) {
                    int4 kk = k4[(jbase >> 2) + q];
                    int j = jbase + q * 4;
                    hit |= ((kk.x == key) & (j     > t) & (j     < nloc)) |
                           ((kk.y == key) & (j + 1 > t) & (j + 1 < nloc)) |
                           ((kk.z == key) & (j + 2 > t) & (j + 2 < nloc)) |
                           ((kk.w == key) & (j + 3 > t) & (j + 3 < nloc));
                }
                if (hit) swin[tl] = 0;   // benign race: same value
            }
        }
        __syncthreads();

        float sbox = 0.0f, scls = 0.0f, scorr = 0.0f, fcnt = 0.0f;

        int task2 = task_lo + tid;
        if (task2 < ntask2) {
            int ch   = task2 & 7;
            int task = task2 >> 3;
            int t = task / NANCH;
            int a = task - t * NANCH;
            int key = keys[t];
            if (key >= 0 && swin[t - t0]) {
                const float* r = tg + t * 6;
                int b = (int)r[0];
                int c = (int)r[1];
                int cell = key - b * HW;
                float p = pred[(size_t)(b * NCH + a * 8 + ch) * HW + cell];

                if (ch < 2) {
                    float d = sig_fast(p) - r[2 + ch];
                    sbox = d * d;
                } else if (ch < 4) {
                    float d = __expf(p) - r[2 + ch];
                    sbox = d * d;
                } else if (ch == 4) {
                    scorr = 1.0f - 2.0f * sig_fast(p);   // (s-1)^2 - s^2
                    fcnt  = 1.0f;
                } else {
                    float tt = ((ch - 5) == c) ? 1.0f : 0.0f;
                    float d  = sig_fast(p) - tt;
                    scls = d * d;
                }
            }
        }

        #pragma unroll
        for (int o = 16; o; o >>= 1) {
            sbox  += __shfl_xor_sync(0xffffffffu, sbox, o);
            scls  += __shfl_xor_sync(0xffffffffu, scls, o);
            scorr += __shfl_xor_sync(0xffffffffu, scorr, o);
            fcnt  += __shfl_xor_sync(0xffffffffu, fcnt, o);
        }
        if (lane == 0) {
            shv[0][w] = sbox; shv[1][w] = scls; shv[2][w] = scorr; shv[3][w] = fcnt;
        }
        __syncthreads();
        if (tid == 0) {
            float tb = 0, tc = 0, tr = 0, tn = 0;
            #pragma unroll
            for (int i = 0; i < 8; ++i) {
                tb += shv[0][i]; tc += shv[1][i]; tr += shv[2][i]; tn += shv[3][i];
            }
            g_sparse[sb][0] = tb;
            g_sparse[sb][1] = tc;
            g_sparse[sb][2] = tr;
            g_sparse[sb][3] = tn;
        }
    }

    // ============ last-arriving block folds everything =======================
    if (tid == 0) {
        __threadfence();
        s_ticket = atomicAdd(&g_count, 1);
    }
    __syncthreads();
    if (s_ticket != nblocks - 1) return;
    __threadfence();

    float sconf = 0.0f;
    if (tid < nconf) sconf = *(volatile float*)&g_partials[tid];

    float tb = 0, tc = 0, tr = 0, tn = 0;
    if (tid < nspb) {
        volatile float* rowp = &g_sparse[tid][0];
        tb = rowp[0]; tc = rowp[1]; tr = rowp[2]; tn = rowp[3];
    }

    #pragma unroll
    for (int o = 16; o; o >>= 1) {
        sconf += __shfl_xor_sync(0xffffffffu, sconf, o);
        tb    += __shfl_xor_sync(0xffffffffu, tb, o);
        tc    += __shfl_xor_sync(0xffffffffu, tc, o);
        tr    += __shfl_xor_sync(0xffffffffu, tr, o);
        tn    += __shfl_xor_sync(0xffffffffu, tn, o);
    }
    __syncthreads();
    if (lane == 0) {
        shf[w] = sconf;
        shv[0][w] = tb; shv[1][w] = tc; shv[2][w] = tr; shv[3][w] = tn;
    }
    __syncthreads();

    if (tid == 0) {
        float tf = 0, b2 = 0, c2 = 0, r2 = 0, n2 = 0;
        #pragma unroll
        for (int i = 0; i < 8; ++i) {
            tf += shf[i];
            b2 += shv[0][i]; c2 += shv[1][i]; r2 += shv[2][i]; n2 += shv[3][i];
        }
        float loss_box  = b2 / (n2 * 4.0f);
        float loss_cls  = c2 / (n2 * (float)NCLS);
        float total     = (float)B * (float)NANCH * (float)HW;
        float loss_conf = (tf + r2) / total;
        out[0] = 5.0f * loss_box + loss_conf + loss_cls;
        g_count = 0;   // reset for next graph replay
    }
}

extern "C" void kernel_launch(void* const* d_in, const int* in_sizes, int n_in,
                              void* d_out, int out_size) {
    const float* pred    = (const float*)d_in[0];
    const float* targets = (const float*)d_in[1];
    int B = in_sizes[0] / (NCH * HW);   // 32
    int N = in_sizes[1] / 6;            // 512
    float* out = (float*)d_out;

    int nconf  = B * NANCH;                            // 96
    int ntask2 = N * NANCH * 8;                        // 12288
    int nspb = (ntask2 + NTHREADS - 1) / NTHREADS;     // 48
    if (nspb > MAX_SPB) nspb = MAX_SPB;
    int nblocks = nconf + nspb;                        // 144

    cudaFuncSetAttribute(fused_kernel,
                         cudaFuncAttributeMaxDynamicSharedMemorySize, SMEM_DYN);
    fused_kernel<<<nblocks, NTHREADS, SMEM_DYN>>>(pred, targets, B, N,
                                                  nconf, nspb, nblocks, out);
}

// round 12
// speedup vs baseline: 15.5882x; 1.0331x over previous
#include <cuda_runtime.h>
#include <cstdint>

// Fixed-shape problem: pred (B=32, 24, 160, 160) fp32, targets (N=512, 6)
#define HGT   160
#define WID   160
#define HW    (HGT * WID)            // 25600
#define NANCH 3
#define NCLS  3
#define NCH   24

#define NTHREADS   256
#define PLANE_B    (HW * 4)          // 102400 bytes per conf plane
#define CHUNK_B    20480             // bulk-copy chunk
#define CHUNK_F4   (CHUNK_B / 16)    // 1280 float4
#define NCHUNKS    5                 // 5 * 20480 = 102400
#define NSTAGE     3
#define SMEM_DYN   (NSTAGE * CHUNK_B)   // 61440 bytes
#define MAX_TGT    2048
#define MAX_SPB    64
#define MAX_LOCAL  16

// Scratch (device globals; no allocation allowed). Overwritten every call.
__device__ float g_partials[NANCH * 64];     // one per conf plane (<=192)
__device__ float g_sparse[MAX_SPB][4];       // {sbox, scls, scorr, count}
__device__ int   g_count = 0;                // reset by fold block each launch

__device__ __forceinline__ float tanh_fast(float x) {
    float r;
    asm("tanh.approx.f32 %0, %1;" : "=f"(r) : "f"(x));
    return r;
}
// sigmoid(x) = 0.5*tanh(0.5x) + 0.5   (one MUFU op)
__device__ __forceinline__ float sig_fast(float x) {
    return fmaf(0.5f, tanh_fast(0.5f * x), 0.5f);
}

__device__ __forceinline__ uint32_t smem_u32(const void* p) {
    return (uint32_t)__cvta_generic_to_shared(p);
}

__device__ __forceinline__ void mbar_init(uint32_t mbar, uint32_t cnt) {
    asm volatile("mbarrier.init.shared.b64 [%0], %1;" :: "r"(mbar), "r"(cnt) : "memory");
}
__device__ __forceinline__ void mbar_expect_tx(uint32_t mbar, uint32_t bytes) {
    asm volatile("mbarrier.arrive.expect_tx.shared.b64 _, [%0], %1;"
                 :: "r"(mbar), "r"(bytes) : "memory");
}
__device__ __forceinline__ void mbar_wait(uint32_t mbar, uint32_t parity) {
    asm volatile(
        "{\n\t"
        ".reg .pred P;\n\t"
        "WAIT_%=:\n\t"
        "mbarrier.try_wait.parity.acquire.cta.shared::cta.b64 P, [%0], %1, 0x989680;\n\t"
        "@P bra.uni DONE_%=;\n\t"
        "bra.uni WAIT_%=;\n\t"
        "DONE_%=:\n\t"
        "}"
        :: "r"(mbar), "r"(parity) : "memory");
}
__device__ __forceinline__ void bulk_g2s(uint32_t dst_smem, const void* src_gmem,
                                         uint32_t bytes, uint32_t mbar) {
    asm volatile(
        "cp.async.bulk.shared::cta.global.mbarrier::complete_tx::bytes "
        "[%0], [%1], %2, [%3];"
        :: "r"(dst_smem), "l"(src_gmem), "r"(bytes), "r"(mbar) : "memory");
}

extern __shared__ float4 dynbuf[];   // conf: 3x20KB stage buffers; sparse: keys

__global__ void __launch_bounds__(NTHREADS)
fused_kernel(const float* __restrict__ pred, const float* __restrict__ tg,
             int B, int N, int nconf, int nspb, int nblocks,
             float* __restrict__ out) {
    __shared__ uint64_t mbar_sto[NSTAGE];
    __shared__ int      swin[MAX_LOCAL];
    __shared__ float    shf[8];
    __shared__ float    shv[4][8];
    __shared__ int      s_ticket;

    const int tid  = threadIdx.x;
    const int bid  = blockIdx.x;
    const int lane = tid & 31, w = tid >> 5;

    if (bid < nconf) {
        // ============ conf block: one plane via cp.async.bulk pipeline =======
        int b = bid / NANCH;
        int a = bid - b * NANCH;
        const char* gsrc = (const char*)pred +
                           (size_t)(b * NCH + a * 8 + 4) * PLANE_B / 1 * 1;
        gsrc = (const char*)pred + (size_t)(b * NCH + a * 8 + 4) * (size_t)PLANE_B;

        uint32_t sbase = smem_u32(dynbuf);
        uint32_t mb0   = smem_u32(&mbar_sto[0]);

        if (tid == 0) {
            #pragma unroll
            for (int s = 0; s < NSTAGE; ++s) mbar_init(mb0 + 8 * s, 1);
        }
        __syncthreads();

        if (tid == 0) {
            #pragma unroll
            for (int s = 0; s < NSTAGE; ++s) {
                mbar_expect_tx(mb0 + 8 * s, CHUNK_B);
                bulk_g2s(sbase + s * CHUNK_B, gsrc + s * CHUNK_B, CHUNK_B,
                         mb0 + 8 * s);
            }
        }

        float acc = 0.0f;
        #pragma unroll
        for (int c = 0; c < NCHUNKS; ++c) {
            int s = c % NSTAGE;
            mbar_wait(mb0 + 8 * s, (c / NSTAGE) & 1);

            const float4* buf = dynbuf + s * CHUNK_F4 + tid;
            float4 v0 = buf[0];
            float4 v1 = buf[256];
            float4 v2 = buf[512];
            float4 v3 = buf[768];
            float4 v4 = buf[1024];
            float sg;
            #define SACC(x) { sg = sig_fast(x); acc = fmaf(sg, sg, acc); }
            SACC(v0.x) SACC(v0.y) SACC(v0.z) SACC(v0.w)
            SACC(v1.x) SACC(v1.y) SACC(v1.z) SACC(v1.w)
            SACC(v2.x) SACC(v2.y) SACC(v2.z) SACC(v2.w)
            SACC(v3.x) SACC(v3.y) SACC(v3.z) SACC(v3.w)
            SACC(v4.x) SACC(v4.y) SACC(v4.z) SACC(v4.w)
            #undef SACC

            if (c + NSTAGE < NCHUNKS) {
                __syncthreads();   // all reads of stage s done before refill
                if (tid == 0) {
                    mbar_expect_tx(mb0 + 8 * s, CHUNK_B);
                    bulk_g2s(sbase + s * CHUNK_B, gsrc + (c + NSTAGE) * CHUNK_B,
                             CHUNK_B, mb0 + 8 * s);
                }
            }
        }

        #pragma unroll
        for (int o = 16; o; o >>= 1) acc += __shfl_xor_sync(0xffffffffu, acc, o);
        if (lane == 0) shf[w] = acc;
        __syncthreads();
        if (tid == 0) {
            float t = 0.0f;
            #pragma unroll
            for (int i = 0; i < 8; ++i) t += shf[i];
            g_partials[bid] = t;
        }
    } else {
        // ============ sparse block (cooperative dedup, 1 thread/(t,a,ch)) ====
        int* keys = (int*)dynbuf;
        int nloc = (N < MAX_TGT) ? N : MAX_TGT;
        int sb   = bid - nconf;

        for (int t = tid; t < nloc; t += NTHREADS) {
            const float* r = tg + t * 6;
            int b  = (int)r[0];
            int gx = (int)(r[2] * (float)WID);
            int gy = (int)(r[3] * (float)HGT);
            bool valid = (gx >= 0) & (gx < WID) & (gy >= 0) & (gy < HGT) &
                         (b >= 0) & (b < B);
            keys[t] = valid ? (b * HW + gy * WID + gx) : -1;
        }
        if (tid < MAX_LOCAL) swin[tid] = 1;
        __syncthreads();

        int task_lo = sb * NTHREADS;
        int task_hi = task_lo + NTHREADS - 1;
        int ntask2  = nloc * NANCH * 8;
        if (task_hi >= ntask2) task_hi = ntask2 - 1;
        int t0 = task_lo / (NANCH * 8);
        int t1 = (task_hi >= task_lo) ? task_hi / (NANCH * 8) : t0 - 1;
        int nlocal = t1 - t0 + 1;

        if (nlocal > 0) {
            int nchunk = (nloc + 15) >> 4;
            int nitems = nlocal * nchunk;
            const int4* k4 = (const int4*)keys;
            for (int item = tid; item < nitems; item += NTHREADS) {
                int tl    = item / nchunk;
                int chunk = item - tl * nchunk;
                int t     = t0 + tl;
                int key   = keys[t];
                if (key < 0) continue;
                int jbase = chunk << 4;
                bool hit = false;
                #pragma unroll
                for (int q = 0; q < 4; ++q) {
                    int4 kk = k4[(jbase >> 2) + q];
                    int j = jbase + q * 4;
                    hit |= ((kk.x == key) & (j     > t) & (j     < nloc)) |
                           ((kk.y == key) & (j + 1 > t) & (j + 1 < nloc)) |
                           ((kk.z == key) & (j + 2 > t) & (j + 2 < nloc)) |
                           ((kk.w == key) & (j + 3 > t) & (j + 3 < nloc));
                }
                if (hit) swin[tl] = 0;   // benign race: same value
            }
        }
        __syncthreads();

        float sbox = 0.0f, scls = 0.0f, scorr = 0.0f, fcnt = 0.0f;

        int task2 = task_lo + tid;
        if (task2 < ntask2) {
            int ch   = task2 & 7;
            int task = task2 >> 3;
            int t = task / NANCH;
            int a = task - t * NANCH;
            int key = keys[t];
            if (key >= 0 && swin[t - t0]) {
                const float* r = tg + t * 6;
                int b = (int)r[0];
                int c = (int)r[1];
                int cell = key - b * HW;
                float p = pred[(size_t)(b * NCH + a * 8 + ch) * HW + cell];

                if (ch < 2) {
                    float d = sig_fast(p) - r[2 + ch];
                    sbox = d * d;
                } else if (ch < 4) {
                    float d = __expf(p) - r[2 + ch];
                    sbox = d * d;
                } else if (ch == 4) {
                    scorr = 1.0f - 2.0f * sig_fast(p);   // (s-1)^2 - s^2
                    fcnt  = 1.0f;
                } else {
                    float tt = ((ch - 5) == c) ? 1.0f : 0.0f;
                    float d  = sig_fast(p) - tt;
                    scls = d * d;
                }
            }
        }

        #pragma unroll
        for (int o = 16; o; o >>= 1) {
            sbox  += __shfl_xor_sync(0xffffffffu, sbox, o);
            scls  += __shfl_xor_sync(0xffffffffu, scls, o);
            scorr += __shfl_xor_sync(0xffffffffu, scorr, o);
            fcnt  += __shfl_xor_sync(0xffffffffu, fcnt, o);
        }
        if (lane == 0) {
            shv[0][w] = sbox; shv[1][w] = scls; shv[2][w] = scorr; shv[3][w] = fcnt;
        }
        __syncthreads();
        if (tid == 0) {
            float tb = 0, tc = 0, tr = 0, tn = 0;
            #pragma unroll
            for (int i = 0; i < 8; ++i) {
                tb += shv[0][i]; tc += shv[1][i]; tr += shv[2][i]; tn += shv[3][i];
            }
            g_sparse[sb][0] = tb;
            g_sparse[sb][1] = tc;
            g_sparse[sb][2] = tr;
            g_sparse[sb][3] = tn;
        }
    }

    // ============ last-arriving block folds everything =======================
    if (tid == 0) {
        __threadfence();
        s_ticket = atomicAdd(&g_count, 1);
    }
    __syncthreads();
    if (s_ticket != nblocks - 1) return;
    __threadfence();

    float sconf = 0.0f;
    if (tid < nconf) sconf = *(volatile float*)&g_partials[tid];

    float tb = 0, tc = 0, tr = 0, tn = 0;
    if (tid < nspb) {
        volatile float* rowp = &g_sparse[tid][0];
        tb = rowp[0]; tc = rowp[1]; tr = rowp[2]; tn = rowp[3];
    }

    #pragma unroll
    for (int o = 16; o; o >>= 1) {
        sconf += __shfl_xor_sync(0xffffffffu, sconf, o);
        tb    += __shfl_xor_sync(0xffffffffu, tb, o);
        tc    += __shfl_xor_sync(0xffffffffu, tc, o);
        tr    += __shfl_xor_sync(0xffffffffu, tr, o);
        tn    += __shfl_xor_sync(0xffffffffu, tn, o);
    }
    __syncthreads();
    if (lane == 0) {
        shf[w] = sconf;
        shv[0][w] = tb; shv[1][w] = tc; shv[2][w] = tr; shv[3][w] = tn;
    }
    __syncthreads();

    if (tid == 0) {
        float tf = 0, b2 = 0, c2 = 0, r2 = 0, n2 = 0;
        #pragma unroll
        for (int i = 0; i < 8; ++i) {
            tf += shf[i];
            b2 += shv[0][i]; c2 += shv[1][i]; r2 += shv[2][i]; n2 += shv[3][i];
        }
        float loss_box  = b2 / (n2 * 4.0f);
        float loss_cls  = c2 / (n2 * (float)NCLS);
        float total     = (float)B * (float)NANCH * (float)HW;
        float loss_conf = (tf + r2) / total;
        out[0] = 5.0f * loss_box + loss_conf + loss_cls;
        g_count = 0;   // reset for next graph replay
    }
}

extern "C" void kernel_launch(void* const* d_in, const int* in_sizes, int n_in,
                              void* d_out, int out_size) {
    const float* pred    = (const float*)d_in[0];
    const float* targets = (const float*)d_in[1];
    int B = in_sizes[0] / (NCH * HW);   // 32
    int N = in_sizes[1] / 6;            // 512
    float* out = (float*)d_out;

    int nconf  = B * NANCH;                            // 96
    int ntask2 = N * NANCH * 8;                        // 12288
    int nspb = (ntask2 + NTHREADS - 1) / NTHREADS;     // 48
    if (nspb > MAX_SPB) nspb = MAX_SPB;
    int nblocks = nconf + nspb;                        // 144

    cudaFuncSetAttribute(fused_kernel,
                         cudaFuncAttributeMaxDynamicSharedMemorySize, SMEM_DYN);
    fused_kernel<<<nblocks, NTHREADS, SMEM_DYN>>>(pred, targets, B, N,
                                                  nconf, nspb, nblocks, out);
}